// round 5
// baseline (speedup 1.0000x reference)
#include <cuda_runtime.h>

// PLE encoding, 1M x 64 f32 out (256 MB) -> HBM-write-bound.
// Per-bin identity: r = clamp((x-lo)*inv, bound_lo, bound_hi) where bounds are
// [0,1] for interior bins, [-inf,1] for bin 0, [0,+inf] for bin 63.
// R4: interior bins use single-instruction fma.rn.sat (free [0,1] clamp);
// only k==0 / k==7 of each 8-bin group carry asymmetric bounds (2 regs).
// -> constants drop 32->18 floats, regs ~40->~30, occupancy back up
//    (more stores in flight). Streaming stores (st.global.cs) keep the
//    never-re-read output from churning L2.

#define N_BINS 64

__device__ __forceinline__ float fma_sat(float a, float b, float c) {
    float r;
    asm("fma.rn.sat.f32 %0, %1, %2, %3;" : "=f"(r) : "f"(a), "f"(b), "f"(c));
    return r;
}

__device__ __forceinline__ void stg256_cs(float* p,
                                          float r0, float r1, float r2, float r3,
                                          float r4, float r5, float r6, float r7)
{
    asm volatile(
        "st.global.cs.v8.f32 [%0], {%1, %2, %3, %4, %5, %6, %7, %8};"
        :: "l"(p),
           "f"(r0), "f"(r1), "f"(r2), "f"(r3),
           "f"(r4), "f"(r5), "f"(r6), "f"(r7)
        : "memory");
}

__global__ __launch_bounds__(256) void ple_kernel(
    const float* __restrict__ x,
    const float* __restrict__ bins,
    float* __restrict__ out,
    int batch)
{
    const int t       = blockIdx.x * blockDim.x + threadIdx.x;
    const int lane8   = t & 7;          // which 8-bin group of the row
    const int group0  = t >> 3;         // starting element index
    const int ngroups = (gridDim.x * blockDim.x) >> 3;
    const int j0      = lane8 << 3;

    const float NEG_INF = __int_as_float(0xff800000u);
    const float POS_INF = __int_as_float(0x7f800000u);

    // Per-thread bin constants (8 bins): slope/offset only.
    float inv[8], c[8];
#pragma unroll
    for (int k = 0; k < 8; k++) {
        const int j  = j0 + k;
        const float lo = __ldg(&bins[j]);
        const float hi = __ldg(&bins[j + 1]);
        const float iv = 1.0f / (hi - lo);
        inv[k] = iv;
        c[k]   = -lo * iv;                       // v = x*inv + c
    }
    // Asymmetric bounds only at group edges (global bins 0 and 63).
    const float lob0 = (j0 == 0)              ? NEG_INF : 0.0f;  // k==0
    const float hib7 = (j0 + 7 == N_BINS - 1) ? POS_INF : 1.0f;  // k==7

#pragma unroll 4
    for (int i = group0; i < batch; i += ngroups) {
        const float xv = __ldg(&x[i]);
        float r[8];
        r[0] = fminf(fmaxf(fmaf(xv, inv[0], c[0]), lob0), 1.0f);
#pragma unroll
        for (int k = 1; k < 7; k++)
            r[k] = fma_sat(xv, inv[k], c[k]);
        r[7] = fminf(fmaxf(fmaf(xv, inv[7], c[7]), 0.0f), hib7);

        float* p = out + (long long)i * N_BINS + j0;
        stg256_cs(p, r[0], r[1], r[2], r[3], r[4], r[5], r[6], r[7]);
    }
}

extern "C" void kernel_launch(void* const* d_in, const int* in_sizes, int n_in,
                              void* d_out, int out_size)
{
    const float* x    = (const float*)d_in[0];
    const float* bins = (const float*)d_in[1];
    float* out        = (float*)d_out;

    const int batch   = in_sizes[0];   // 1,000,000
    const int threads = 256;
    const int blocks  = 2048;          // 65536 groups -> ~15 elems/thread

    ple_kernel<<<blocks, threads>>>(x, bins, out, batch);
}